// round 10
// baseline (speedup 1.0000x reference)
#include <cuda_runtime.h>

// Problem constants: B=64, D=2048, UNITS=1024, NW=64
#define Dd     2048
#define UNITSn 1024
#define NWn    64

#define UPC    8                 // units per CTA
#define NCTA   (UNITSn / UPC)    // 128 CTAs
#define BKt    64                // k-tile width (8B operands, small live state)
#define NT     (Dd / BKt)        // 32 tiles
#define NTHR   512               // 16 warps = 4 per SMSP
#define NROW   4                 // batch rows per thread (rows z + 16r)
#define RPAD   33                // reduce-buffer row stride (conflict-free)

__device__ __forceinline__ void fma2(unsigned long long& d,
                                     unsigned long long a,
                                     unsigned long long b) {
    asm("fma.rn.f32x2 %0, %1, %2, %0;" : "+l"(d) : "l"(a), "l"(b));
}
__device__ __forceinline__ unsigned mdiv(unsigned e, unsigned magic) {
    return (unsigned)(((unsigned long long)e * magic) >> 32);
}

// ---------------------------------------------------------------------------
// Fused hashed-linear, v4: 4 warps/SMSP AND a 2-tile register pipeline — the
// combination R7 (4 w/SMSP, 1-deep) and R9 (2 w/SMSP, 2-deep) each half-had.
// Phase 1: build 8 dense W rows (8 x 2048 fp32, 64KB) in smem from the hashed
//          index lists (int4 loads, 16 LDG.128 in flight per thread).
// Phase 2: barrier-free GEMM. Warp z in [0,16) owns rows {z,z+16,z+32,z+48};
//          lane owns k-offset 2*lane of each 64-wide tile. x direct from L2
//          via coalesced LDG.64, 2 tiles ahead (768-cyc cover vs ~250 L2 lat).
//          W from smem in two 4-unit LDS.64 batches (caps register liveness:
//          acc 64 + xpipe 24 + wv 8 + addr ~ 116 regs, under the 128 cap).
// Epilogue: k lives entirely in lanes and rows are warp-exclusive, so the
//           reduction is warp-local via padded smem; + bias; no atomics.
// ---------------------------------------------------------------------------
__global__ __launch_bounds__(NTHR, 1) void fused_kernel(const float* __restrict__ x,
                                                        const float* __restrict__ w,
                                                        const float* __restrict__ bias,
                                                        const int* __restrict__ indices,
                                                        float* __restrict__ out,
                                                        int L, unsigned magicL) {
    extern __shared__ float sm[];
    float* ws  = sm;                 // [UPC][Dd] = 64KB (overlaid by reduce buf later)
    float* wsm = sm + UPC * Dd;      // [NWn]     (dead after phase 1)

    const int tid  = threadIdx.x;
    const int lane = tid & 31;
    const int z    = tid >> 5;                // warp id: rows z + 16r
    const int u0   = blockIdx.x * UPC;
    const int koff = lane * 2;                // this lane's k offset within a tile

    // Issue tiles 0 and 1 of x NOW; cold-miss latency hides under phase 1.
    const float* xp = x + (long)z * Dd + koff;       // rows step by 16*Dd
    unsigned long long xa[NROW], xb[NROW];
    #pragma unroll
    for (int r = 0; r < NROW; r++) {
        xa[r] = *(const unsigned long long*)(xp + (long)r * 16 * Dd);
        xb[r] = *(const unsigned long long*)(xp + (long)r * 16 * Dd + BKt);
    }

    // ---- Phase 1: build W rows in smem ----
    if (tid < NWn) wsm[tid] = w[tid];
    const float4 z4 = make_float4(0.f, 0.f, 0.f, 0.f);
    #pragma unroll
    for (int i = 0; i < (UPC * Dd / 4) / NTHR; i++)
        ((float4*)ws)[i * NTHR + tid] = z4;          // zero 64KB
    __syncthreads();

    {
        const int NWL4 = 16 * L;                     // int4 count per unit
        const int4* ind4 = (const int4*)indices + (long)u0 * NWL4;
        int e4 = tid;
        // Paired iterations: 16 independent LDG.128 in flight.
        for (; e4 + NTHR < NWL4; e4 += 2 * NTHR) {
            int4 v[UPC], v2[UPC];
            #pragma unroll
            for (int uu = 0; uu < UPC; uu++) {
                v[uu]  = __ldg(ind4 + (long)uu * NWL4 + e4);
                v2[uu] = __ldg(ind4 + (long)uu * NWL4 + e4 + NTHR);
            }
            #pragma unroll
            for (int h = 0; h < 2; h++) {
                const int4* vv = h ? v2 : v;
                const int e = (e4 + h * NTHR) * 4;
                const unsigned k0 = mdiv(e,     magicL);
                const unsigned k1 = mdiv(e + 1, magicL);
                const unsigned k2 = mdiv(e + 2, magicL);
                const unsigned k3 = mdiv(e + 3, magicL);
                #pragma unroll
                for (int uu = 0; uu < UPC; uu++) {
                    float* wrow = ws + uu * Dd;
                    unsigned p;
                    p = (unsigned)(vv[uu].x - 1); if (p < (unsigned)Dd) wrow[p] = wsm[k0];
                    p = (unsigned)(vv[uu].y - 1); if (p < (unsigned)Dd) wrow[p] = wsm[k1];
                    p = (unsigned)(vv[uu].z - 1); if (p < (unsigned)Dd) wrow[p] = wsm[k2];
                    p = (unsigned)(vv[uu].w - 1); if (p < (unsigned)Dd) wrow[p] = wsm[k3];
                }
            }
        }
        for (; e4 < NWL4; e4 += NTHR) {
            int4 v[UPC];
            #pragma unroll
            for (int uu = 0; uu < UPC; uu++)
                v[uu] = __ldg(ind4 + (long)uu * NWL4 + e4);
            const int e = e4 * 4;
            const unsigned k0 = mdiv(e,     magicL);
            const unsigned k1 = mdiv(e + 1, magicL);
            const unsigned k2 = mdiv(e + 2, magicL);
            const unsigned k3 = mdiv(e + 3, magicL);
            #pragma unroll
            for (int uu = 0; uu < UPC; uu++) {
                float* wrow = ws + uu * Dd;
                unsigned p;
                p = (unsigned)(v[uu].x - 1); if (p < (unsigned)Dd) wrow[p] = wsm[k0];
                p = (unsigned)(v[uu].y - 1); if (p < (unsigned)Dd) wrow[p] = wsm[k1];
                p = (unsigned)(v[uu].z - 1); if (p < (unsigned)Dd) wrow[p] = wsm[k2];
                p = (unsigned)(v[uu].w - 1); if (p < (unsigned)Dd) wrow[p] = wsm[k3];
            }
        }
    }
    __syncthreads();   // ws ready; mainloop is barrier-free from here

    // ---- Phase 2: GEMM, x direct from L2, 2-tile lookahead, 4 warps/SMSP ----
    unsigned long long acc[NROW][UPC];
    #pragma unroll
    for (int r = 0; r < NROW; r++)
        #pragma unroll
        for (int j = 0; j < UPC; j++) acc[r][j] = 0ULL;    // (0.0f, 0.0f)

    #pragma unroll 2
    for (int t = 0; t < NT; t++) {
        // Issue tile t+2's 4 coalesced LDG.64 first (2-tile lookahead).
        unsigned long long xc[NROW];
        if (t + 2 < NT) {
            #pragma unroll
            for (int r = 0; r < NROW; r++)
                xc[r] = *(const unsigned long long*)(xp + (long)r * 16 * Dd
                                                     + (t + 2) * BKt);
        }

        const float* wk = ws + t * BKt + koff;

        // Two 4-unit batches keep wv liveness at 4 regs pairs (reg cap 128).
        #pragma unroll
        for (int g = 0; g < 2; g++) {
            unsigned long long wv[4];
            #pragma unroll
            for (int j = 0; j < 4; j++)
                wv[j] = *(const unsigned long long*)(wk + (g * 4 + j) * Dd);
            #pragma unroll
            for (int j = 0; j < 4; j++)
                #pragma unroll
                for (int r = 0; r < NROW; r++)
                    fma2(acc[r][g * 4 + j], xa[r], wv[j]);
        }

        #pragma unroll
        for (int r = 0; r < NROW; r++) { xa[r] = xb[r]; xb[r] = xc[r]; }
    }
    __syncthreads();   // all ws reads done; safe to overlay reduce buffer

    // ---- Epilogue: warp-local k-reduction via padded smem, + bias ----
    float* red = sm;   // [16*32][RPAD] = 67.6KB (overlays ws + wsm)
    #pragma unroll
    for (int r = 0; r < NROW; r++)
        #pragma unroll
        for (int j = 0; j < UPC; j++) {
            unsigned long long v = acc[r][j];
            float s = __uint_as_float((unsigned)(v & 0xffffffffu)) +
                      __uint_as_float((unsigned)(v >> 32));
            red[(z * 32 + lane) * RPAD + r * UPC + j] = s;   // conflict-free
        }
    __syncthreads();

    // One output per thread: producing warp oz, slot rj -> (r, j).
    const int oz = tid >> 5;
    const int rj = tid & 31;
    float s = 0.f;
    #pragma unroll
    for (int l = 0; l < 32; l++)
        s += red[(oz * 32 + l) * RPAD + rj];   // bank = (l + rj) % 32: conflict-free
    const int r = rj >> 3;
    const int j = rj & 7;
    s += __ldg(bias + u0 + j);
    out[(long)(oz + 16 * r) * UNITSn + u0 + j] = s;
}

// ---------------------------------------------------------------------------
extern "C" void kernel_launch(void* const* d_in, const int* in_sizes, int n_in,
                              void* d_out, int out_size) {
    const float* x       = (const float*)d_in[0];
    const float* w       = (const float*)d_in[1];
    const float* bias    = (const float*)d_in[2];
    const int*   indices = (const int*)d_in[3];
    float*       out     = (float*)d_out;

    const int L = in_sizes[3] / (UNITSn * NWn);
    const unsigned magicL =
        (unsigned)((0x100000000ULL + (unsigned long long)L - 1) / (unsigned long long)L);

    // smem = max(ws + wsm, reduce buffer) = 512*33 floats = 67,584 B
    const int smem_bytes = (NTHR * RPAD) * (int)sizeof(float);
    cudaFuncSetAttribute(fused_kernel, cudaFuncAttributeMaxDynamicSharedMemorySize,
                         smem_bytes);

    fused_kernel<<<NCTA, NTHR, smem_bytes>>>(x, w, bias, indices, out, L, magicL);
}